// round 13
// baseline (speedup 1.0000x reference)
#include <cuda_runtime.h>
#include <cuda_fp16.h>
#include <mma.h>
#include <cstdint>
#include <cstddef>
#include <math.h>

using namespace nvcuda;

// Problem constants
#define Bb 4
#define Ll 4096
#define Dd 2048
#define HD 64
#define MTOT (Bb * Ll)   // 16384

// ---------------------------------------------------------------------------
// Scratch (device globals; no allocation allowed)
// ---------------------------------------------------------------------------
__device__ __half g_x16[(size_t)MTOT * Dd];        // fp16 X
__device__ __half g_w16[4][(size_t)Dd * Dd];       // fp16 Wq/Wk/Wv/Wo
__device__ __half g_q16[(size_t)MTOT * Dd];        // fp16 Q (pre-bias/rope)
__device__ __half g_k16[(size_t)MTOT * Dd];
__device__ __half g_v16[(size_t)MTOT * Dd];
__device__ __half g_o16[(size_t)MTOT * Dd];        // fp16 attention output (reshuffled)
__device__ float  g_cos[Ll * 32];
__device__ float  g_sin[Ll * 32];

// ---------------------------------------------------------------------------
// RoPE table
// ---------------------------------------------------------------------------
__global__ void rope_table_kernel() {
    int l = blockIdx.x;
    int d = threadIdx.x;
    float p = powf(10000.0f, (float)d * (1.0f / 32.0f));
    float theta = 1.0f / p;
    float ang = (float)l * theta;
    float s, c;
    sincosf(ang, &s, &c);
    g_cos[l * 32 + d] = c;
    g_sin[l * 32 + d] = s;
}

// ---------------------------------------------------------------------------
// f32 -> fp16 conversions (one pass)
// ---------------------------------------------------------------------------
__global__ void __launch_bounds__(256)
convX_kernel(const float* __restrict__ src) {
    size_t i = (size_t)blockIdx.x * 256 + threadIdx.x;   // float4 index
    float4 v = ((const float4*)src)[i];
    ((__half2*)g_x16)[2 * i]     = __floats2half2_rn(v.x, v.y);
    ((__half2*)g_x16)[2 * i + 1] = __floats2half2_rn(v.z, v.w);
}

__global__ void __launch_bounds__(256)
convW_kernel(const float* __restrict__ wq, const float* __restrict__ wk,
             const float* __restrict__ wv, const float* __restrict__ wo) {
    size_t i = (size_t)blockIdx.x * 256 + threadIdx.x;   // float4 index over 4 matrices
    int sel = (int)(i >> 20);                            // Dd*Dd/4 = 2^20 float4 per matrix
    size_t loc = i & ((1u << 20) - 1);
    const float* s = (sel == 0) ? wq : (sel == 1) ? wk : (sel == 2) ? wv : wo;
    float4 v = ((const float4*)s)[loc];
    __half* dst = g_w16[sel];
    ((__half2*)dst)[2 * loc]     = __floats2half2_rn(v.x, v.y);
    ((__half2*)dst)[2 * loc + 1] = __floats2half2_rn(v.z, v.w);
}

// ---------------------------------------------------------------------------
// FP16 wmma GEMM core:  acc[128x256] += A[128xK] @ W[256xK]^T
// CTA tile 128x256x64, 8 warps (2M x 4N), warp tile 64x64.
// 3 smem buffers (BK=64), cp.async issued right after the barrier so GMEM
// loads overlap the full 4-subtile compute block. Half the sync density of
// the BK=32 version.
// ---------------------------------------------------------------------------
#define BM 128
#define BN 256
#define BK 64
#define BKP 72                         // padded row stride in halves (144 B)
#define STGH ((BM + BN) * BKP)         // halves per stage = 27648 (55296 B)
#define NIT (Dd / BK)                  // 32
#define NSTAGE 3
#define DYN_SMEM (NSTAGE * STGH * 2)   // 165888 bytes

__device__ __forceinline__ void cpa16(const __half* smem, const __half* gmem) {
    unsigned a = (unsigned)__cvta_generic_to_shared(smem);
    asm volatile("cp.async.cg.shared.global [%0], [%1], 16;\n" :: "r"(a), "l"(gmem));
}

__device__ __forceinline__ void load_stage(const __half* __restrict__ A,
                                           const __half* __restrict__ W,
                                           __half* s, int bm, int bn,
                                           int k0, int tid) {
#pragma unroll
    for (int i = 0; i < 4; i++) {                 // A: 128 rows x 8 chunks = 1024
        int c = tid + i * 256;
        int r = c >> 3, sg = c & 7;
        cpa16(s + r * BKP + sg * 8, A + (size_t)(bm + r) * Dd + k0 + sg * 8);
    }
#pragma unroll
    for (int i = 0; i < 8; i++) {                 // B: 256 rows x 8 chunks = 2048
        int c = tid + i * 256;
        int r = c >> 3, sg = c & 7;
        cpa16(s + BM * BKP + r * BKP + sg * 8, W + (size_t)(bn + r) * Dd + k0 + sg * 8);
    }
}

using AccFrag = wmma::fragment<wmma::accumulator, 16, 16, 16, float>;

__device__ __forceinline__ void gemm_mainloop(const __half* __restrict__ A,
                                              const __half* __restrict__ Bw,
                                              __half* smem, int bm, int bnl,
                                              int tid, int wm, int wn,
                                              AccFrag acc[4][4]) {
#pragma unroll
    for (int i = 0; i < 4; i++)
#pragma unroll
        for (int j = 0; j < 4; j++)
            wmma::fill_fragment(acc[i][j], 0.0f);

    // Prologue: stages 0,1
#pragma unroll
    for (int p = 0; p < 2; p++) {
        load_stage(A, Bw, smem + p * STGH, bm, bnl, p * BK, tid);
        asm volatile("cp.async.commit_group;" ::: "memory");
    }

    int buf = 0;
    for (int it = 0; it < NIT; ++it) {
        asm volatile("cp.async.wait_group 1;" ::: "memory");
        __syncthreads();

        // Kick off the load for stage it+2 immediately; it lands in the
        // buffer whose reads completed before the barrier above.
        int L = it + 2;
        int wbuf = buf + 2 >= NSTAGE ? buf + 2 - NSTAGE : buf + 2;
        if (L < NIT)
            load_stage(A, Bw, smem + wbuf * STGH, bm, bnl, L * BK, tid);
        asm volatile("cp.async.commit_group;" ::: "memory");   // always commit

        const __half* sa = smem + buf * STGH;
        const __half* sb = sa + BM * BKP;

#pragma unroll
        for (int kf = 0; kf < 4; ++kf) {
            wmma::fragment<wmma::matrix_a, 16, 16, 16, __half, wmma::row_major> af[4];
            wmma::fragment<wmma::matrix_b, 16, 16, 16, __half, wmma::col_major> bf[4];
#pragma unroll
            for (int i = 0; i < 4; i++)
                wmma::load_matrix_sync(af[i], sa + (wm + i * 16) * BKP + kf * 16, BKP);
#pragma unroll
            for (int j = 0; j < 4; j++)
                wmma::load_matrix_sync(bf[j], sb + (wn + j * 16) * BKP + kf * 16, BKP);
#pragma unroll
            for (int i = 0; i < 4; i++)
#pragma unroll
                for (int j = 0; j < 4; j++)
                    wmma::mma_sync(acc[i][j], af[i], bf[j], acc[i][j]);
        }

        if (++buf == NSTAGE) buf = 0;
    }
    __syncthreads();   // all wmma reads done before epilogue reuses smem
}

// ---------------------------------------------------------------------------
// Fused QKV GEMM: N = 6144 (Wq|Wk|Wv stacked); fp16 output via smem staging.
// ---------------------------------------------------------------------------
__global__ void __launch_bounds__(256, 1)
gemm_qkv(void) {
    extern __shared__ __align__(16) __half smem[];

    int tid = threadIdx.x;
    int bm = blockIdx.y * BM;
    int bng = blockIdx.x * BN;            // global column in [0, 6144)
    int wsel = bng >> 11;                 // 0=q 1=k 2=v
    int bnl = bng & 2047;                 // column within the 2048-wide matrix
    const __half* Bw = g_w16[wsel];
    __half* out16 = (wsel == 0) ? g_q16 : (wsel == 1) ? g_k16 : g_v16;

    int wid = tid >> 5, lane = tid & 31;
    int wm = (wid & 1) * 64;
    int wn = (wid >> 1) * 64;

    AccFrag acc[4][4];
    gemm_mainloop(g_x16, Bw, smem, bm, bnl, tid, wm, wn, acc);

    // Epilogue: stage 16x64 f32 per warp in smem, convert to fp16, store.
    float* stg = (float*)smem + wid * 1024;      // 16*64 floats = 4KB per warp
    int r = lane >> 1;
    int c0 = (lane & 1) * 32;
#pragma unroll
    for (int i = 0; i < 4; i++) {
#pragma unroll
        for (int j = 0; j < 4; j++)
            wmma::store_matrix_sync(stg + j * 16, acc[i][j], 64, wmma::mem_row_major);
        const float4* sf4 = (const float4*)(stg + r * 64 + c0);
        int gr = bm + wm + i * 16 + r;
        int gc = bnl + wn + c0;
        uint4* gdst = (uint4*)(out16 + (size_t)gr * Dd + gc);
#pragma unroll
        for (int q4 = 0; q4 < 4; q4++) {
            float4 a = sf4[2 * q4], b = sf4[2 * q4 + 1];
            union { __half2 h[4]; uint4 u; } pk;
            pk.h[0] = __floats2half2_rn(a.x, a.y);
            pk.h[1] = __floats2half2_rn(a.z, a.w);
            pk.h[2] = __floats2half2_rn(b.x, b.y);
            pk.h[3] = __floats2half2_rn(b.z, b.w);
            gdst[q4] = pk.u;
        }
        __syncwarp();
    }
}

// ---------------------------------------------------------------------------
// Output GEMM: d_out = o16 @ Wo^T + bo   (f32 output, bias fused in epilogue)
// ---------------------------------------------------------------------------
__global__ void __launch_bounds__(256, 1)
gemm_o(float* __restrict__ Y, const float* __restrict__ bo) {
    extern __shared__ __align__(16) __half smem[];

    int tid = threadIdx.x;
    int bm = blockIdx.y * BM;
    int bn = blockIdx.x * BN;
    int wid = tid >> 5, lane = tid & 31;
    int wm = (wid & 1) * 64;
    int wn = (wid >> 1) * 64;

    AccFrag acc[4][4];
    gemm_mainloop(g_o16, g_w16[3], smem, bm, bn, tid, wm, wn, acc);

    // Epilogue: stage, add bias, store f32.
    float* stg = (float*)smem + wid * 1024;
    int r = lane >> 1;
    int c0 = (lane & 1) * 32;
    int gc = bn + wn + c0;

    float4 bb[8];
    const float4* bo4 = (const float4*)(bo + gc);
#pragma unroll
    for (int t = 0; t < 8; t++) bb[t] = bo4[t];

#pragma unroll
    for (int i = 0; i < 4; i++) {
#pragma unroll
        for (int j = 0; j < 4; j++)
            wmma::store_matrix_sync(stg + j * 16, acc[i][j], 64, wmma::mem_row_major);
        const float4* sf4 = (const float4*)(stg + r * 64 + c0);
        int gr = bm + wm + i * 16 + r;
        float4* gdst = (float4*)(Y + (size_t)gr * Dd + gc);
#pragma unroll
        for (int t = 0; t < 8; t++) {
            float4 v = sf4[t];
            v.x += bb[t].x; v.y += bb[t].y; v.z += bb[t].z; v.w += bb[t].w;
            gdst[t] = v;
        }
        __syncwarp();
    }
}

// ---------------------------------------------------------------------------
// Attention over heads axis, fused bias + RoPE, packed f32x2 math.
// One warp per (b,l). lane = head h. Reads fp16 q/k/v; writes fp16 o16 in the
// reshuffled layout: o16[b][h*128 + l/32][(l%32)*64 + d].
// ---------------------------------------------------------------------------
union F2U { float2 f; unsigned long long u; };

__device__ __forceinline__ void ffma2(F2U& acc, F2U a, F2U b) {
    asm("fma.rn.f32x2 %0, %1, %2, %0;" : "+l"(acc.u) : "l"(a.u), "l"(b.u));
}

__device__ __forceinline__ void h8_to_f(uint4 u, float* f) {
    const __half2* h = (const __half2*)&u;
#pragma unroll
    for (int t = 0; t < 4; t++) {
        float2 x = __half22float2(h[t]);
        f[2 * t] = x.x;
        f[2 * t + 1] = x.y;
    }
}

__global__ void __launch_bounds__(64)
attn_kernel(const float* __restrict__ bq, const float* __restrict__ bk,
            const float* __restrict__ bv) {
    __shared__ __align__(16) float ksh[2][32][64];
    __shared__ __align__(16) float vsh[2][32][64];
    __shared__ float csh[2][32];
    __shared__ float ssh[2][32];

    int w = threadIdx.x >> 5;
    int lane = threadIdx.x & 31;
    int pos = blockIdx.x * 2 + w;
    int l = pos & (Ll - 1);
    int b = pos >> 12;
    size_t base = (size_t)pos * Dd + (size_t)lane * HD;

    csh[w][lane] = g_cos[l * 32 + lane];
    ssh[w][lane] = g_sin[l * 32 + lane];
    __syncwarp();

    // --- K: load fp16, bias, rope, stage to smem
    {
        const uint4* kr = (const uint4*)(g_k16 + base);
        const float4* bk4 = (const float4*)(bk + lane * HD);
        float kf[64];
#pragma unroll
        for (int j = 0; j < 8; j++) h8_to_f(kr[j], kf + 8 * j);
#pragma unroll
        for (int j = 0; j < 16; j++) {
            float4 bb = bk4[j];
            kf[4 * j + 0] += bb.x; kf[4 * j + 1] += bb.y;
            kf[4 * j + 2] += bb.z; kf[4 * j + 3] += bb.w;
        }
#pragma unroll
        for (int d = 0; d < 32; d++) {
            float c = csh[w][d], s = ssh[w][d];
            float lo = kf[d], hi = kf[d + 32];
            ksh[w][lane][d]      = lo * c - hi * s;
            ksh[w][lane][d + 32] = hi * c + lo * s;
        }
    }
    // --- V: load fp16, bias, stage to smem
    {
        const uint4* vr = (const uint4*)(g_v16 + base);
        const float4* bv4 = (const float4*)(bv + lane * HD);
        float vf[64];
#pragma unroll
        for (int j = 0; j < 8; j++) h8_to_f(vr[j], vf + 8 * j);
#pragma unroll
        for (int j = 0; j < 16; j++) {
            float4 bb = bv4[j];
            vf[4 * j + 0] += bb.x; vf[4 * j + 1] += bb.y;
            vf[4 * j + 2] += bb.z; vf[4 * j + 3] += bb.w;
        }
#pragma unroll
        for (int d = 0; d < 64; d++) vsh[w][lane][d] = vf[d];
    }

    // --- Q row (bias + rope) into registers
    float qv[64];
    {
        const uint4* qr = (const uint4*)(g_q16 + base);
        const float4* bq4 = (const float4*)(bq + lane * HD);
        float qf[64];
#pragma unroll
        for (int j = 0; j < 8; j++) h8_to_f(qr[j], qf + 8 * j);
#pragma unroll
        for (int j = 0; j < 16; j++) {
            float4 bb = bq4[j];
            qf[4 * j + 0] += bb.x; qf[4 * j + 1] += bb.y;
            qf[4 * j + 2] += bb.z; qf[4 * j + 3] += bb.w;
        }
#pragma unroll
        for (int d = 0; d < 32; d++) {
            float c = csh[w][d], s = ssh[w][d];
            float lo = qf[d], hi = qf[d + 32];
            qv[d]      = lo * c - hi * s;
            qv[d + 32] = hi * c + lo * s;
        }
    }
    __syncwarp();

    int h = lane;

    // --- scores (causal: g <= h)
    float sc[32];
    float mx = -1e30f;
#pragma unroll
    for (int g = 0; g < 32; ++g) {
        if (g <= h) {
            F2U acc; acc.f = make_float2(0.0f, 0.0f);
            const float4* kr = (const float4*)&ksh[w][g][0];
#pragma unroll
            for (int j = 0; j < 16; j++) {
                float4 kk = kr[j];
                F2U a1, b1, a2, b2;
                a1.f = make_float2(qv[4 * j + 0], qv[4 * j + 1]);
                b1.f = make_float2(kk.x, kk.y);
                ffma2(acc, a1, b1);
                a2.f = make_float2(qv[4 * j + 2], qv[4 * j + 3]);
                b2.f = make_float2(kk.z, kk.w);
                ffma2(acc, a2, b2);
            }
            float s_ = (acc.f.x + acc.f.y) * 0.125f;   // 1/sqrt(64)
            sc[g] = s_;
            mx = fmaxf(mx, s_);
        }
    }

    float denom = 0.0f;
#pragma unroll
    for (int g = 0; g < 32; ++g) {
        if (g <= h) {
            float e = expf(sc[g] - mx);
            sc[g] = e;
            denom += e;
        }
    }
    float inv = 1.0f / denom;

    F2U ov[32];
#pragma unroll
    for (int j = 0; j < 32; j++) ov[j].f = make_float2(0.0f, 0.0f);
#pragma unroll
    for (int g = 0; g < 32; ++g) {
        if (g <= h) {
            F2U aa; aa.f = make_float2(sc[g], sc[g]);
            const float4* vr = (const float4*)&vsh[w][g][0];
#pragma unroll
            for (int j = 0; j < 16; j++) {
                float4 vv = vr[j];
                F2U b1, b2;
                b1.f = make_float2(vv.x, vv.y);
                b2.f = make_float2(vv.z, vv.w);
                ffma2(ov[2 * j], aa, b1);
                ffma2(ov[2 * j + 1], aa, b2);
            }
        }
    }

    // Store fp16 into reshuffled layout for the output GEMM (16B stores)
    __half* orow = g_o16 + ((size_t)(b * 4096 + h * 128 + (l >> 5)) * Dd + (l & 31) * HD);
    uint4* orow16 = (uint4*)orow;
#pragma unroll
    for (int j = 0; j < 8; j++) {
        union { __half2 hh[4]; uint4 u; } pk;
        pk.hh[0] = __floats2half2_rn(ov[4 * j + 0].f.x * inv, ov[4 * j + 0].f.y * inv);
        pk.hh[1] = __floats2half2_rn(ov[4 * j + 1].f.x * inv, ov[4 * j + 1].f.y * inv);
        pk.hh[2] = __floats2half2_rn(ov[4 * j + 2].f.x * inv, ov[4 * j + 2].f.y * inv);
        pk.hh[3] = __floats2half2_rn(ov[4 * j + 3].f.x * inv, ov[4 * j + 3].f.y * inv);
        orow16[j] = pk.u;
    }
}

// ---------------------------------------------------------------------------
// Launch
// ---------------------------------------------------------------------------
extern "C" void kernel_launch(void* const* d_in, const int* in_sizes, int n_in,
                              void* d_out, int out_size) {
    const float* x  = (const float*)d_in[0];
    const float* Wq = (const float*)d_in[1];
    const float* bq = (const float*)d_in[2];
    const float* Wk = (const float*)d_in[3];
    const float* bk = (const float*)d_in[4];
    const float* Wv = (const float*)d_in[5];
    const float* bv = (const float*)d_in[6];
    const float* Wo = (const float*)d_in[7];
    const float* bo = (const float*)d_in[8];
    float* out = (float*)d_out;

    (void)in_sizes; (void)n_in; (void)out_size;

    cudaFuncSetAttribute(gemm_qkv, cudaFuncAttributeMaxDynamicSharedMemorySize, DYN_SMEM);
    cudaFuncSetAttribute(gemm_o,   cudaFuncAttributeMaxDynamicSharedMemorySize, DYN_SMEM);

    rope_table_kernel<<<Ll, 32>>>();

    convX_kernel<<<(MTOT * Dd) / (4 * 256), 256>>>(x);
    convW_kernel<<<(4 * Dd * Dd) / (4 * 256), 256>>>(Wq, Wk, Wv, Wo);

    dim3 gqkv(3 * Dd / BN, MTOT / BM);   // (24, 128)
    gemm_qkv<<<gqkv, 256, DYN_SMEM>>>();

    attn_kernel<<<(Bb * Ll) / 2, 64>>>(bq, bk, bv);

    dim3 go(Dd / BN, MTOT / BM);         // (8, 128)
    gemm_o<<<go, 256, DYN_SMEM>>>(out, bo);
}

// round 14
// speedup vs baseline: 1.0820x; 1.0820x over previous
#include <cuda_runtime.h>
#include <cuda_fp16.h>
#include <mma.h>
#include <cstdint>
#include <cstddef>
#include <math.h>

using namespace nvcuda;

// Problem constants
#define Bb 4
#define Ll 4096
#define Dd 2048
#define HD 64
#define MTOT (Bb * Ll)   // 16384

// ---------------------------------------------------------------------------
// Scratch (device globals; no allocation allowed)
// ---------------------------------------------------------------------------
__device__ __half g_x16[(size_t)MTOT * Dd];        // fp16 X
__device__ __half g_w16[4][(size_t)Dd * Dd];       // fp16 Wq/Wk/Wv/Wo
__device__ __half g_q16[(size_t)MTOT * Dd];        // fp16 Q (pre-bias/rope)
__device__ __half g_k16[(size_t)MTOT * Dd];
__device__ __half g_v16[(size_t)MTOT * Dd];
__device__ __half g_o16[(size_t)MTOT * Dd];        // fp16 attention output (reshuffled)
__device__ float  g_cos[Ll * 32];
__device__ float  g_sin[Ll * 32];

// ---------------------------------------------------------------------------
// RoPE table
// ---------------------------------------------------------------------------
__global__ void rope_table_kernel() {
    int l = blockIdx.x;
    int d = threadIdx.x;
    float p = powf(10000.0f, (float)d * (1.0f / 32.0f));
    float theta = 1.0f / p;
    float ang = (float)l * theta;
    float s, c;
    sincosf(ang, &s, &c);
    g_cos[l * 32 + d] = c;
    g_sin[l * 32 + d] = s;
}

// ---------------------------------------------------------------------------
// f32 -> fp16 conversions (one pass)
// ---------------------------------------------------------------------------
__global__ void __launch_bounds__(256)
convX_kernel(const float* __restrict__ src) {
    size_t i = (size_t)blockIdx.x * 256 + threadIdx.x;   // float4 index
    float4 v = ((const float4*)src)[i];
    ((__half2*)g_x16)[2 * i]     = __floats2half2_rn(v.x, v.y);
    ((__half2*)g_x16)[2 * i + 1] = __floats2half2_rn(v.z, v.w);
}

__global__ void __launch_bounds__(256)
convW_kernel(const float* __restrict__ wq, const float* __restrict__ wk,
             const float* __restrict__ wv, const float* __restrict__ wo) {
    size_t i = (size_t)blockIdx.x * 256 + threadIdx.x;   // float4 index over 4 matrices
    int sel = (int)(i >> 20);                            // Dd*Dd/4 = 2^20 float4 per matrix
    size_t loc = i & ((1u << 20) - 1);
    const float* s = (sel == 0) ? wq : (sel == 1) ? wk : (sel == 2) ? wv : wo;
    float4 v = ((const float4*)s)[loc];
    __half* dst = g_w16[sel];
    ((__half2*)dst)[2 * loc]     = __floats2half2_rn(v.x, v.y);
    ((__half2*)dst)[2 * loc + 1] = __floats2half2_rn(v.z, v.w);
}

// ---------------------------------------------------------------------------
// FP16 wmma GEMM core:  acc[128x128] += A[128xK] @ W[128xK]^T
// CTA tile 128x128x32, 8 warps (4M x 2N), warp tile 32x64 -> 64 acc regs,
// so 2 CTAs/SM (16 warps/SM) fit the register file. 4 smem buffers,
// 3-deep cp.async pipeline (R10-proven loop structure).
// ---------------------------------------------------------------------------
#define BM 128
#define BN 128
#define BK 32
#define BKP 40                         // padded row stride in halves (80 B)
#define STGH ((BM + BN) * BKP)         // halves per stage = 10240 (20480 B)
#define NIT (Dd / BK)                  // 64
#define DYN_SMEM (4 * STGH * 2)        // 81920 bytes -> 2 CTAs/SM

__device__ __forceinline__ void cpa16(const __half* smem, const __half* gmem) {
    unsigned a = (unsigned)__cvta_generic_to_shared(smem);
    asm volatile("cp.async.cg.shared.global [%0], [%1], 16;\n" :: "r"(a), "l"(gmem));
}

__device__ __forceinline__ void load_stage(const __half* __restrict__ A,
                                           const __half* __restrict__ W,
                                           __half* s, int bm, int bn,
                                           int k0, int tid) {
#pragma unroll
    for (int i = 0; i < 2; i++) {                 // A: 128 rows x 4 chunks = 512
        int c = tid + i * 256;
        int r = c >> 2, sg = c & 3;
        cpa16(s + r * BKP + sg * 8, A + (size_t)(bm + r) * Dd + k0 + sg * 8);
    }
#pragma unroll
    for (int i = 0; i < 2; i++) {                 // B: 128 rows x 4 chunks = 512
        int c = tid + i * 256;
        int r = c >> 2, sg = c & 3;
        cpa16(s + BM * BKP + r * BKP + sg * 8, W + (size_t)(bn + r) * Dd + k0 + sg * 8);
    }
}

using AccFrag = wmma::fragment<wmma::accumulator, 16, 16, 16, float>;

__device__ __forceinline__ void gemm_mainloop(const __half* __restrict__ A,
                                              const __half* __restrict__ Bw,
                                              __half* smem, int bm, int bnl,
                                              int tid, int wm, int wn,
                                              AccFrag acc[2][4]) {
#pragma unroll
    for (int i = 0; i < 2; i++)
#pragma unroll
        for (int j = 0; j < 4; j++)
            wmma::fill_fragment(acc[i][j], 0.0f);

    // Prologue: stages 0..2
#pragma unroll
    for (int p = 0; p < 3; p++) {
        load_stage(A, Bw, smem + p * STGH, bm, bnl, p * BK, tid);
        asm volatile("cp.async.commit_group;" ::: "memory");
    }

    for (int it = 0; it < NIT; ++it) {
        asm volatile("cp.async.wait_group 2;" ::: "memory");
        __syncthreads();

        const __half* sa = smem + (it & 3) * STGH;
        const __half* sb = sa + BM * BKP;

#pragma unroll
        for (int kf = 0; kf < 2; ++kf) {
            wmma::fragment<wmma::matrix_a, 16, 16, 16, __half, wmma::row_major> af[2];
            wmma::fragment<wmma::matrix_b, 16, 16, 16, __half, wmma::col_major> bf[4];
#pragma unroll
            for (int i = 0; i < 2; i++)
                wmma::load_matrix_sync(af[i], sa + (wm + i * 16) * BKP + kf * 16, BKP);
#pragma unroll
            for (int j = 0; j < 4; j++)
                wmma::load_matrix_sync(bf[j], sb + (wn + j * 16) * BKP + kf * 16, BKP);
#pragma unroll
            for (int i = 0; i < 2; i++)
#pragma unroll
                for (int j = 0; j < 4; j++)
                    wmma::mma_sync(acc[i][j], af[i], bf[j], acc[i][j]);
        }

        int L = it + 3;
        if (L < NIT)
            load_stage(A, Bw, smem + (L & 3) * STGH, bm, bnl, L * BK, tid);
        asm volatile("cp.async.commit_group;" ::: "memory");   // always commit
    }
    __syncthreads();   // all wmma reads done before epilogue reuses smem
}

// ---------------------------------------------------------------------------
// Fused QKV GEMM: N = 6144 (Wq|Wk|Wv stacked); fp16 output via smem staging.
// ---------------------------------------------------------------------------
__global__ void __launch_bounds__(256, 2)
gemm_qkv(void) {
    extern __shared__ __align__(16) __half smem[];

    int tid = threadIdx.x;
    int bm = blockIdx.y * BM;
    int bng = blockIdx.x * BN;            // global column in [0, 6144)
    int wsel = bng >> 11;                 // 0=q 1=k 2=v
    int bnl = bng & 2047;                 // column within the 2048-wide matrix
    const __half* Bw = g_w16[wsel];
    __half* out16 = (wsel == 0) ? g_q16 : (wsel == 1) ? g_k16 : g_v16;

    int wid = tid >> 5, lane = tid & 31;
    int wm = (wid & 3) * 32;              // 4 warps in M
    int wn = (wid >> 2) * 64;             // 2 warps in N

    AccFrag acc[2][4];
    gemm_mainloop(g_x16, Bw, smem, bm, bnl, tid, wm, wn, acc);

    // Epilogue: stage 16x64 f32 per warp in smem, convert to fp16, store.
    float* stg = (float*)smem + wid * 1024;      // 16*64 floats = 4KB per warp
    int r = lane >> 1;
    int c0 = (lane & 1) * 32;
#pragma unroll
    for (int i = 0; i < 2; i++) {
#pragma unroll
        for (int j = 0; j < 4; j++)
            wmma::store_matrix_sync(stg + j * 16, acc[i][j], 64, wmma::mem_row_major);
        const float4* sf4 = (const float4*)(stg + r * 64 + c0);
        int gr = bm + wm + i * 16 + r;
        int gc = bnl + wn + c0;
        uint4* gdst = (uint4*)(out16 + (size_t)gr * Dd + gc);
#pragma unroll
        for (int q4 = 0; q4 < 4; q4++) {
            float4 a = sf4[2 * q4], b = sf4[2 * q4 + 1];
            union { __half2 h[4]; uint4 u; } pk;
            pk.h[0] = __floats2half2_rn(a.x, a.y);
            pk.h[1] = __floats2half2_rn(a.z, a.w);
            pk.h[2] = __floats2half2_rn(b.x, b.y);
            pk.h[3] = __floats2half2_rn(b.z, b.w);
            gdst[q4] = pk.u;
        }
        __syncwarp();
    }
}

// ---------------------------------------------------------------------------
// Output GEMM: d_out = o16 @ Wo^T + bo   (f32 output, bias fused in epilogue)
// ---------------------------------------------------------------------------
__global__ void __launch_bounds__(256, 2)
gemm_o(float* __restrict__ Y, const float* __restrict__ bo) {
    extern __shared__ __align__(16) __half smem[];

    int tid = threadIdx.x;
    int bm = blockIdx.y * BM;
    int bn = blockIdx.x * BN;
    int wid = tid >> 5, lane = tid & 31;
    int wm = (wid & 3) * 32;
    int wn = (wid >> 2) * 64;

    AccFrag acc[2][4];
    gemm_mainloop(g_o16, g_w16[3], smem, bm, bn, tid, wm, wn, acc);

    // Epilogue: stage, add bias, store f32.
    float* stg = (float*)smem + wid * 1024;
    int r = lane >> 1;
    int c0 = (lane & 1) * 32;
    int gc = bn + wn + c0;

    float4 bb[8];
    const float4* bo4 = (const float4*)(bo + gc);
#pragma unroll
    for (int t = 0; t < 8; t++) bb[t] = bo4[t];

#pragma unroll
    for (int i = 0; i < 2; i++) {
#pragma unroll
        for (int j = 0; j < 4; j++)
            wmma::store_matrix_sync(stg + j * 16, acc[i][j], 64, wmma::mem_row_major);
        const float4* sf4 = (const float4*)(stg + r * 64 + c0);
        int gr = bm + wm + i * 16 + r;
        float4* gdst = (float4*)(Y + (size_t)gr * Dd + gc);
#pragma unroll
        for (int t = 0; t < 8; t++) {
            float4 v = sf4[t];
            v.x += bb[t].x; v.y += bb[t].y; v.z += bb[t].z; v.w += bb[t].w;
            gdst[t] = v;
        }
        __syncwarp();
    }
}

// ---------------------------------------------------------------------------
// Attention over heads axis, fused bias + RoPE, packed f32x2 math.
// One warp per (b,l). lane = head h. Reads fp16 q/k/v; writes fp16 o16 in the
// reshuffled layout: o16[b][h*128 + l/32][(l%32)*64 + d].
// ---------------------------------------------------------------------------
union F2U { float2 f; unsigned long long u; };

__device__ __forceinline__ void ffma2(F2U& acc, F2U a, F2U b) {
    asm("fma.rn.f32x2 %0, %1, %2, %0;" : "+l"(acc.u) : "l"(a.u), "l"(b.u));
}

__device__ __forceinline__ void h8_to_f(uint4 u, float* f) {
    const __half2* h = (const __half2*)&u;
#pragma unroll
    for (int t = 0; t < 4; t++) {
        float2 x = __half22float2(h[t]);
        f[2 * t] = x.x;
        f[2 * t + 1] = x.y;
    }
}

__global__ void __launch_bounds__(64)
attn_kernel(const float* __restrict__ bq, const float* __restrict__ bk,
            const float* __restrict__ bv) {
    __shared__ __align__(16) float ksh[2][32][64];
    __shared__ __align__(16) float vsh[2][32][64];
    __shared__ float csh[2][32];
    __shared__ float ssh[2][32];

    int w = threadIdx.x >> 5;
    int lane = threadIdx.x & 31;
    int pos = blockIdx.x * 2 + w;
    int l = pos & (Ll - 1);
    int b = pos >> 12;
    size_t base = (size_t)pos * Dd + (size_t)lane * HD;

    csh[w][lane] = g_cos[l * 32 + lane];
    ssh[w][lane] = g_sin[l * 32 + lane];
    __syncwarp();

    // --- K: load fp16, bias, rope, stage to smem
    {
        const uint4* kr = (const uint4*)(g_k16 + base);
        const float4* bk4 = (const float4*)(bk + lane * HD);
        float kf[64];
#pragma unroll
        for (int j = 0; j < 8; j++) h8_to_f(kr[j], kf + 8 * j);
#pragma unroll
        for (int j = 0; j < 16; j++) {
            float4 bb = bk4[j];
            kf[4 * j + 0] += bb.x; kf[4 * j + 1] += bb.y;
            kf[4 * j + 2] += bb.z; kf[4 * j + 3] += bb.w;
        }
#pragma unroll
        for (int d = 0; d < 32; d++) {
            float c = csh[w][d], s = ssh[w][d];
            float lo = kf[d], hi = kf[d + 32];
            ksh[w][lane][d]      = lo * c - hi * s;
            ksh[w][lane][d + 32] = hi * c + lo * s;
        }
    }
    // --- V: load fp16, bias, stage to smem
    {
        const uint4* vr = (const uint4*)(g_v16 + base);
        const float4* bv4 = (const float4*)(bv + lane * HD);
        float vf[64];
#pragma unroll
        for (int j = 0; j < 8; j++) h8_to_f(vr[j], vf + 8 * j);
#pragma unroll
        for (int j = 0; j < 16; j++) {
            float4 bb = bv4[j];
            vf[4 * j + 0] += bb.x; vf[4 * j + 1] += bb.y;
            vf[4 * j + 2] += bb.z; vf[4 * j + 3] += bb.w;
        }
#pragma unroll
        for (int d = 0; d < 64; d++) vsh[w][lane][d] = vf[d];
    }

    // --- Q row (bias + rope) into registers
    float qv[64];
    {
        const uint4* qr = (const uint4*)(g_q16 + base);
        const float4* bq4 = (const float4*)(bq + lane * HD);
        float qf[64];
#pragma unroll
        for (int j = 0; j < 8; j++) h8_to_f(qr[j], qf + 8 * j);
#pragma unroll
        for (int j = 0; j < 16; j++) {
            float4 bb = bq4[j];
            qf[4 * j + 0] += bb.x; qf[4 * j + 1] += bb.y;
            qf[4 * j + 2] += bb.z; qf[4 * j + 3] += bb.w;
        }
#pragma unroll
        for (int d = 0; d < 32; d++) {
            float c = csh[w][d], s = ssh[w][d];
            float lo = qf[d], hi = qf[d + 32];
            qv[d]      = lo * c - hi * s;
            qv[d + 32] = hi * c + lo * s;
        }
    }
    __syncwarp();

    int h = lane;

    // --- scores (causal: g <= h)
    float sc[32];
    float mx = -1e30f;
#pragma unroll
    for (int g = 0; g < 32; ++g) {
        if (g <= h) {
            F2U acc; acc.f = make_float2(0.0f, 0.0f);
            const float4* kr = (const float4*)&ksh[w][g][0];
#pragma unroll
            for (int j = 0; j < 16; j++) {
                float4 kk = kr[j];
                F2U a1, b1, a2, b2;
                a1.f = make_float2(qv[4 * j + 0], qv[4 * j + 1]);
                b1.f = make_float2(kk.x, kk.y);
                ffma2(acc, a1, b1);
                a2.f = make_float2(qv[4 * j + 2], qv[4 * j + 3]);
                b2.f = make_float2(kk.z, kk.w);
                ffma2(acc, a2, b2);
            }
            float s_ = (acc.f.x + acc.f.y) * 0.125f;   // 1/sqrt(64)
            sc[g] = s_;
            mx = fmaxf(mx, s_);
        }
    }

    float denom = 0.0f;
#pragma unroll
    for (int g = 0; g < 32; ++g) {
        if (g <= h) {
            float e = expf(sc[g] - mx);
            sc[g] = e;
            denom += e;
        }
    }
    float inv = 1.0f / denom;

    F2U ov[32];
#pragma unroll
    for (int j = 0; j < 32; j++) ov[j].f = make_float2(0.0f, 0.0f);
#pragma unroll
    for (int g = 0; g < 32; ++g) {
        if (g <= h) {
            F2U aa; aa.f = make_float2(sc[g], sc[g]);
            const float4* vr = (const float4*)&vsh[w][g][0];
#pragma unroll
            for (int j = 0; j < 16; j++) {
                float4 vv = vr[j];
                F2U b1, b2;
                b1.f = make_float2(vv.x, vv.y);
                b2.f = make_float2(vv.z, vv.w);
                ffma2(ov[2 * j], aa, b1);
                ffma2(ov[2 * j + 1], aa, b2);
            }
        }
    }

    // Store fp16 into reshuffled layout for the output GEMM (16B stores)
    __half* orow = g_o16 + ((size_t)(b * 4096 + h * 128 + (l >> 5)) * Dd + (l & 31) * HD);
    uint4* orow16 = (uint4*)orow;
#pragma unroll
    for (int j = 0; j < 8; j++) {
        union { __half2 hh[4]; uint4 u; } pk;
        pk.hh[0] = __floats2half2_rn(ov[4 * j + 0].f.x * inv, ov[4 * j + 0].f.y * inv);
        pk.hh[1] = __floats2half2_rn(ov[4 * j + 1].f.x * inv, ov[4 * j + 1].f.y * inv);
        pk.hh[2] = __floats2half2_rn(ov[4 * j + 2].f.x * inv, ov[4 * j + 2].f.y * inv);
        pk.hh[3] = __floats2half2_rn(ov[4 * j + 3].f.x * inv, ov[4 * j + 3].f.y * inv);
        orow16[j] = pk.u;
    }
}

// ---------------------------------------------------------------------------
// Launch
// ---------------------------------------------------------------------------
extern "C" void kernel_launch(void* const* d_in, const int* in_sizes, int n_in,
                              void* d_out, int out_size) {
    const float* x  = (const float*)d_in[0];
    const float* Wq = (const float*)d_in[1];
    const float* bq = (const float*)d_in[2];
    const float* Wk = (const float*)d_in[3];
    const float* bk = (const float*)d_in[4];
    const float* Wv = (const float*)d_in[5];
    const float* bv = (const float*)d_in[6];
    const float* Wo = (const float*)d_in[7];
    const float* bo = (const float*)d_in[8];
    float* out = (float*)d_out;

    (void)in_sizes; (void)n_in; (void)out_size;

    cudaFuncSetAttribute(gemm_qkv, cudaFuncAttributeMaxDynamicSharedMemorySize, DYN_SMEM);
    cudaFuncSetAttribute(gemm_o,   cudaFuncAttributeMaxDynamicSharedMemorySize, DYN_SMEM);

    rope_table_kernel<<<Ll, 32>>>();

    convX_kernel<<<(MTOT * Dd) / (4 * 256), 256>>>(x);
    convW_kernel<<<(4 * Dd * Dd) / (4 * 256), 256>>>(Wq, Wk, Wv, Wo);

    dim3 gqkv(3 * Dd / BN, MTOT / BM);   // (48, 128)
    gemm_qkv<<<gqkv, 256, DYN_SMEM>>>();

    attn_kernel<<<(Bb * Ll) / 2, 64>>>(bq, bk, bv);

    dim3 go(Dd / BN, MTOT / BM);         // (16, 128)
    gemm_o<<<go, 256, DYN_SMEM>>>(out, bo);
}